// round 3
// baseline (speedup 1.0000x reference)
#include <cuda_runtime.h>
#include <math.h>

#define BATCH 8192
#define NC    2048
#define NF    512

// Scratch (no allocations allowed in kernel_launch)
__device__ float g_xsq[BATCH];   // ||x_m||^2
__device__ float g_csq[NC];      // ||c_n||^2
__device__ float g_inv2s[NC];    // 1 / (2 * sigma_n^2)

// One warp per row: sum of squares of NF floats.
__global__ void row_norms_kernel(const float* __restrict__ X,
                                 float* __restrict__ out, int rows) {
    int warps_per_blk = blockDim.x >> 5;
    int row  = blockIdx.x * warps_per_blk + (threadIdx.x >> 5);
    int lane = threadIdx.x & 31;
    if (row >= rows) return;
    const float4* p = reinterpret_cast<const float4*>(X + (size_t)row * NF);
    float s = 0.f;
    #pragma unroll 4
    for (int i = lane; i < NF / 4; i += 32) {
        float4 v = p[i];
        s += v.x * v.x + v.y * v.y + v.z * v.z + v.w * v.w;
    }
    #pragma unroll
    for (int o = 16; o; o >>= 1) s += __shfl_xor_sync(0xffffffffu, s, o);
    if (lane == 0) out[row] = s;
}

__global__ void sigma_kernel(const float* __restrict__ sig,
                             float* __restrict__ out, int n) {
    int i = blockIdx.x * blockDim.x + threadIdx.x;
    if (i < n) {
        float s = sig[i];
        out[i] = 1.0f / (2.0f * s * s);
    }
}

// Register-tiled SGEMM (C = A * B^T), RBF epilogue fused.
// BM=BN=128, BK=16, 256 threads, 8x8 per-thread microtile.
__global__ __launch_bounds__(256, 2)
void rbf_gemm_kernel(const float* __restrict__ A,   // [BATCH, NF]
                     const float* __restrict__ B,   // [NC, NF]
                     const float* __restrict__ xsq,
                     const float* __restrict__ csq,
                     const float* __restrict__ inv2s,
                     float* __restrict__ C)         // [BATCH, NC]
{
    constexpr int BM = 128, BN = 128, BK = 16;
    // Pad so row stride (132 floats = 528B) stays 16B-aligned and spreads banks.
    __shared__ float As[BK][BM + 4];
    __shared__ float Bs[BK][BN + 4];

    const int bx = blockIdx.x;          // N tile
    const int by = blockIdx.y;          // M tile
    const int tid = threadIdx.x;
    const int tx = tid & 15;            // n-direction (0..15)
    const int ty = tid >> 4;            // m-direction (0..15)

    const float* Ab = A + (size_t)by * BM * NF;
    const float* Bb = B + (size_t)bx * BN * NF;

    float acc[8][8];
    #pragma unroll
    for (int m = 0; m < 8; m++)
        #pragma unroll
        for (int n = 0; n < 8; n++) acc[m][n] = 0.f;

    for (int k0 = 0; k0 < NF; k0 += BK) {
        // Each thread loads 2 float4 from A and 2 from B (tile = 512 float4 each).
        #pragma unroll
        for (int i = 0; i < 2; i++) {
            int idx = tid * 2 + i;           // 0..511
            int row = idx >> 2;              // 0..127
            int c4  = idx & 3;               // which float4 within the 16-wide row
            float4 va = *reinterpret_cast<const float4*>(Ab + (size_t)row * NF + k0 + c4 * 4);
            As[c4 * 4 + 0][row] = va.x;
            As[c4 * 4 + 1][row] = va.y;
            As[c4 * 4 + 2][row] = va.z;
            As[c4 * 4 + 3][row] = va.w;
            float4 vb = *reinterpret_cast<const float4*>(Bb + (size_t)row * NF + k0 + c4 * 4);
            Bs[c4 * 4 + 0][row] = vb.x;
            Bs[c4 * 4 + 1][row] = vb.y;
            Bs[c4 * 4 + 2][row] = vb.z;
            Bs[c4 * 4 + 3][row] = vb.w;
        }
        __syncthreads();

        #pragma unroll
        for (int k = 0; k < BK; k++) {
            float ra[8], rb[8];
            #pragma unroll
            for (int m = 0; m < 8; m++) ra[m] = As[k][ty * 8 + m];
            #pragma unroll
            for (int n = 0; n < 8; n++) rb[n] = Bs[k][tx * 8 + n];
            #pragma unroll
            for (int m = 0; m < 8; m++)
                #pragma unroll
                for (int n = 0; n < 8; n++)
                    acc[m][n] = fmaf(ra[m], rb[n], acc[m][n]);
        }
        __syncthreads();
    }

    // Fused RBF epilogue.
    const int m0 = by * BM + ty * 8;
    const int n0 = bx * BN + tx * 8;
    float cn[8], is[8];
    #pragma unroll
    for (int n = 0; n < 8; n++) { cn[n] = csq[n0 + n]; is[n] = inv2s[n0 + n]; }

    #pragma unroll
    for (int m = 0; m < 8; m++) {
        float xm = xsq[m0 + m];
        float res[8];
        #pragma unroll
        for (int n = 0; n < 8; n++) {
            float d = fmaf(-2.0f, acc[m][n], xm + cn[n]);
            d = fmaxf(d, 0.0f);
            res[n] = expf(-d * is[n]);
        }
        float* crow = C + (size_t)(m0 + m) * NC + n0;
        *reinterpret_cast<float4*>(crow + 0) = make_float4(res[0], res[1], res[2], res[3]);
        *reinterpret_cast<float4*>(crow + 4) = make_float4(res[4], res[5], res[6], res[7]);
    }
}

extern "C" void kernel_launch(void* const* d_in, const int* in_sizes, int n_in,
                              void* d_out, int out_size) {
    const float* inputs  = (const float*)d_in[0];   // [8192, 512]
    const float* centers = (const float*)d_in[1];   // [2048, 512]
    const float* sigmas  = (const float*)d_in[2];   // [2048]
    float* out = (float*)d_out;                     // [8192, 2048]

    float *xsq, *csq, *inv2s;
    cudaGetSymbolAddress((void**)&xsq,   g_xsq);
    cudaGetSymbolAddress((void**)&csq,   g_csq);
    cudaGetSymbolAddress((void**)&inv2s, g_inv2s);

    // Norms: one warp per row, 8 warps per block.
    row_norms_kernel<<<BATCH / 8, 256>>>(inputs, xsq, BATCH);
    row_norms_kernel<<<NC / 8, 256>>>(centers, csq, NC);
    sigma_kernel<<<NC / 256, 256>>>(sigmas, inv2s, NC);

    dim3 grid(NC / 128, BATCH / 128);   // (16, 64)
    rbf_gemm_kernel<<<grid, 256>>>(inputs, centers, xsq, csq, inv2s, out);
}